// round 14
// baseline (speedup 1.0000x reference)
#include <cuda_runtime.h>
#include <cuda_fp16.h>
#include <stdint.h>
#include <math.h>

#define NN 100000
#define EE 3200000
#define FF 13
#define HH 64
#define GG 512
#define POOLW 192
#define BN_EPS 1e-5f
#define NBLK 391   /* ceil(NN/256) */

// ---------------- scratch (device globals: allocation-free) ----------------
__device__ int    g_deg[NN];
__device__ int    g_rowptr[NN + 1];
__device__ int    g_rank[EE];
__device__ int    g_col[EE];
__device__ int    g_bsum[512];
__device__ __align__(16) __half g_hA[NN * 64];
__device__ __align__(16) __half g_hB[NN * 64];
__device__ float  g_pool[GG * POOLW];

// ---------------- PTX helpers ----------------
__device__ __forceinline__ void gin_ldsm_a(unsigned int* frag_out4, unsigned int smem_addr_u32) {
    asm volatile("ldmatrix.sync.aligned.m8n8.x4.shared.b16 {%0,%1,%2,%3}, [%4];"
                 : "=r"(frag_out4[0]), "=r"(frag_out4[1]),
                   "=r"(frag_out4[2]), "=r"(frag_out4[3])
                 : "r"(smem_addr_u32));
}

__device__ __forceinline__ void gin_ldsm_bt(unsigned int* frag_out4, unsigned int smem_addr_u32) {
    asm volatile("ldmatrix.sync.aligned.m8n8.x4.trans.shared.b16 {%0,%1,%2,%3}, [%4];"
                 : "=r"(frag_out4[0]), "=r"(frag_out4[1]),
                   "=r"(frag_out4[2]), "=r"(frag_out4[3])
                 : "r"(smem_addr_u32));
}

__device__ __forceinline__ void gin_mma(float* acc_inout4, const unsigned int* frag_a4,
                                        unsigned int frag_b_first, unsigned int frag_b_second) {
    asm volatile(
        "mma.sync.aligned.m16n8k16.row.col.f32.f16.f16.f32 "
        "{%0,%1,%2,%3}, {%4,%5,%6,%7}, {%8,%9}, {%0,%1,%2,%3};"
        : "+f"(acc_inout4[0]), "+f"(acc_inout4[1]),
          "+f"(acc_inout4[2]), "+f"(acc_inout4[3])
        : "r"(frag_a4[0]), "r"(frag_a4[1]), "r"(frag_a4[2]), "r"(frag_a4[3]),
          "r"(frag_b_first), "r"(frag_b_second));
}

// ---------------- CSR build ----------------
__global__ void init_zero_kernel() {
    int i = blockIdx.x * blockDim.x + threadIdx.x;
    if (i < NN) g_deg[i] = 0;
    if (i < GG * POOLW) g_pool[i] = 0.f;
}

// hist + rank: the atomic's return value is this edge's slot within its dst row.
__global__ void hist_kernel(const int* __restrict__ dst) {
    int i = (blockIdx.x * blockDim.x + threadIdx.x) * 8;
    if (i < EE) {  // EE % 8 == 0
        int4 dva = *(const int4*)&dst[i];
        int4 dvb = *(const int4*)&dst[i + 4];
        int r0 = atomicAdd(&g_deg[dva.x], 1);
        int r1 = atomicAdd(&g_deg[dva.y], 1);
        int r2 = atomicAdd(&g_deg[dva.z], 1);
        int r3 = atomicAdd(&g_deg[dva.w], 1);
        int r4 = atomicAdd(&g_deg[dvb.x], 1);
        int r5 = atomicAdd(&g_deg[dvb.y], 1);
        int r6 = atomicAdd(&g_deg[dvb.z], 1);
        int r7 = atomicAdd(&g_deg[dvb.w], 1);
        *(int4*)&g_rank[i]     = make_int4(r0, r1, r2, r3);
        *(int4*)&g_rank[i + 4] = make_int4(r4, r5, r6, r7);
    }
}

// Hierarchical scan, stage 1: per-block (256-wide) exclusive scan + block sums
__global__ void scan_block_kernel() {
    __shared__ int wsum[8];
    int tid = threadIdx.x;
    int i = blockIdx.x * 256 + tid;
    int v = (i < NN) ? g_deg[i] : 0;
    int x = v;
#pragma unroll
    for (int o = 1; o < 32; o <<= 1) {
        int y = __shfl_up_sync(0xffffffffu, x, o);
        if ((tid & 31) >= o) x += y;
    }
    if ((tid & 31) == 31) wsum[tid >> 5] = x;
    __syncthreads();
    if (tid == 0) {
        int run = 0;
#pragma unroll
        for (int w = 0; w < 8; w++) { int tmpv = wsum[w]; wsum[w] = run; run += tmpv; }
        g_bsum[blockIdx.x] = run;
    }
    __syncthreads();
    if (i < NN) g_rowptr[i] = x - v + wsum[tid >> 5];
}

// Stage 2: single-block exclusive scan over the 391 block sums (in place)
__global__ void scan_bsum_kernel() {
    __shared__ int wsum[16];
    int tid = threadIdx.x;   // 512 threads
    int v = (tid < NBLK) ? g_bsum[tid] : 0;
    int x = v;
#pragma unroll
    for (int o = 1; o < 32; o <<= 1) {
        int y = __shfl_up_sync(0xffffffffu, x, o);
        if ((tid & 31) >= o) x += y;
    }
    if ((tid & 31) == 31) wsum[tid >> 5] = x;
    __syncthreads();
    if (tid == 0) {
        int run = 0;
#pragma unroll
        for (int w = 0; w < 16; w++) { int tmpv = wsum[w]; wsum[w] = run; run += tmpv; }
    }
    __syncthreads();
    if (tid < NBLK) g_bsum[tid] = x - v + wsum[tid >> 5];
}

// Stage 3: add block offsets, set rowptr[NN]
__global__ void scan_add_kernel() {
    int tid = threadIdx.x;
    int i = blockIdx.x * 256 + tid;
    if (i < NN) g_rowptr[i] = g_rowptr[i] + g_bsum[blockIdx.x];
    if (i == 0) g_rowptr[NN] = EE;
}

// scatter with precomputed ranks: NO atomics — pure load/store with deep MLP.
__global__ void scatter_kernel(const int* __restrict__ src, const int* __restrict__ dst) {
    int i = (blockIdx.x * blockDim.x + threadIdx.x) * 8;
    if (i < EE) {
        int4 dva = *(const int4*)&dst[i];
        int4 dvb = *(const int4*)&dst[i + 4];
        int4 sva = *(const int4*)&src[i];
        int4 svb = *(const int4*)&src[i + 4];
        int4 rva = *(const int4*)&g_rank[i];
        int4 rvb = *(const int4*)&g_rank[i + 4];
        g_col[g_rowptr[dva.x] + rva.x] = sva.x;
        g_col[g_rowptr[dva.y] + rva.y] = sva.y;
        g_col[g_rowptr[dva.z] + rva.z] = sva.z;
        g_col[g_rowptr[dva.w] + rva.w] = sva.w;
        g_col[g_rowptr[dvb.x] + rvb.x] = svb.x;
        g_col[g_rowptr[dvb.y] + rvb.y] = svb.y;
        g_col[g_rowptr[dvb.z] + rvb.z] = svb.z;
        g_col[g_rowptr[dvb.w] + rvb.w] = svb.w;
    }
}

// smem layout constants
#define SMEM_ROW_H 72   /* half elements per row (144B): ldmatrix conflict-free */
#define POOL_ROW_F 68   /* float elements per row of pool staging */

// ---------------- layer 1: FIN=13 fp32 input; 512 threads, forced 2 blocks/SM ----------------
__global__ void __launch_bounds__(512, 2)
gin_layer_first_kernel(const float* __restrict__ xin,
                       const float* __restrict__ W1, const float* __restrict__ b1,
                       const float* __restrict__ gam, const float* __restrict__ bet,
                       const float* __restrict__ mu, const float* __restrict__ var,
                       const float* __restrict__ W2, const float* __restrict__ b2,
                       const int* __restrict__ batch,
                       __half* __restrict__ hout, int pool_off) {
    __shared__ __align__(16) __half As[64 * SMEM_ROW_H];
    __shared__ __align__(16) __half W1s[64 * SMEM_ROW_H];
    __shared__ __align__(16) __half W2s[64 * SMEM_ROW_H];
    __shared__ float  Ps[64 * POOL_ROW_F];
    __shared__ float  sc1[64], sh1[64], b2s[64];
    __shared__ int    bgid[64];

    int tid = threadIdx.x;
    int node0 = blockIdx.x * 64;
    int warp = tid >> 5, lane = tid & 31;

    for (int idx = tid; idx < 16 * 64; idx += 512) {
        int krow = idx >> 6, ncol = idx & 63;
        W1s[krow * SMEM_ROW_H + ncol] = __float2half((krow < FF) ? W1[krow * 64 + ncol] : 0.f);
    }
    for (int idx = tid; idx < 64 * 64; idx += 512) {
        int krow = idx >> 6, ncol = idx & 63;
        W2s[krow * SMEM_ROW_H + ncol] = __float2half(W2[krow * 64 + ncol]);
    }
    if (tid < 64) {
        float bn_scale = gam[tid] * rsqrtf(var[tid] + BN_EPS);
        sc1[tid] = bn_scale;
        sh1[tid] = fmaf(b1[tid] - mu[tid], bn_scale, bet[tid]);
        b2s[tid] = b2[tid];
        int node = node0 + tid;
        bgid[tid] = batch[(node < NN) ? node : (NN - 1)];
    }

    // rowptr warp prefetch: lanes 0..4 load rowptr[warp_base .. warp_base+4]
    int rp_pref = 0;
    {
        int idxp = node0 + warp * 4 + lane;
        if (lane < 5) rp_pref = g_rowptr[(idxp <= NN) ? idxp : NN];
    }

    // gather: 8-wide edge unroll + index prefetch
#pragma unroll 1
    for (int i = 0; i < 4; i++) {
        int r = warp * 4 + i;
        int node = node0 + r;
        int s = __shfl_sync(0xffffffffu, rp_pref, i);
        int e = __shfl_sync(0xffffffffu, rp_pref, i + 1);
        float acc = 0.f;
        if (node < NN && lane < FF) acc = xin[node * FF + lane];
        if (node < NN) {
            int cidx = (s + lane < e) ? g_col[s + lane] : 0;
#pragma unroll 1
            for (int cb = s; cb < e; cb += 32) {
                int cnt = min(32, e - cb);
                int cidx_next = (cb + 32 + lane < e) ? g_col[cb + 32 + lane] : 0;
                int t = 0;
                for (; t + 8 <= cnt; t += 8) {
                    int jj[8];
#pragma unroll
                    for (int q = 0; q < 8; q++) jj[q] = __shfl_sync(0xffffffffu, cidx, t + q);
                    if (lane < FF) {
                        float vv[8];
#pragma unroll
                        for (int q = 0; q < 8; q++) vv[q] = xin[jj[q] * FF + lane];
                        acc += ((vv[0] + vv[1]) + (vv[2] + vv[3])) +
                               ((vv[4] + vv[5]) + (vv[6] + vv[7]));
                    }
                }
                for (; t < cnt; t++) {
                    int j = __shfl_sync(0xffffffffu, cidx, t);
                    if (lane < FF) acc += xin[j * FF + lane];
                }
                cidx = cidx_next;
            }
        }
        if (lane < 16) As[r * SMEM_ROW_H + lane] = __float2half((lane < FF) ? acc : 0.f);
    }
    __syncthreads();

    int mma_row = warp & 3;            // rows (warp&3)*16..+15
    int mma_col = (warp >> 2) * 16;    // 16 cols per warp
    unsigned int base_as = (unsigned int)__cvta_generic_to_shared(As);
    unsigned int base_w1 = (unsigned int)__cvta_generic_to_shared(W1s);
    unsigned int base_w2 = (unsigned int)__cvta_generic_to_shared(W2s);
    int off_a = (mma_row * 16 + (lane & 15)) * SMEM_ROW_H + ((lane >> 4) << 3);
    int off_w = (lane & 15) * SMEM_ROW_H + mma_col + ((lane >> 4) << 3);

    // GEMM1 (KPAD=16 -> single k-chunk); each warp: 16x16 output tile
    float acc1[2][4];
#pragma unroll
    for (int i = 0; i < 2; i++)
#pragma unroll
        for (int j = 0; j < 4; j++) acc1[i][j] = 0.f;
    {
        unsigned int frag_a[4];
        unsigned int frag_b[4];
        gin_ldsm_a(frag_a, base_as + (unsigned int)(off_a * 2));
        gin_ldsm_bt(frag_b, base_w1 + (unsigned int)(off_w * 2));
        gin_mma(acc1[0], frag_a, frag_b[0], frag_b[1]);
        gin_mma(acc1[1], frag_a, frag_b[2], frag_b[3]);
    }
    __syncthreads();

    // epilogue1: BN+ReLU -> As (fp16)
    {
        int row_out = mma_row * 16 + (lane >> 2);
#pragma unroll
        for (int j = 0; j < 2; j++) {
            int c = mma_col + j * 8 + ((lane & 3) << 1);
            float o00 = fmaxf(fmaf(acc1[j][0], sc1[c],     sh1[c]),     0.f);
            float o01 = fmaxf(fmaf(acc1[j][1], sc1[c + 1], sh1[c + 1]), 0.f);
            float o10 = fmaxf(fmaf(acc1[j][2], sc1[c],     sh1[c]),     0.f);
            float o11 = fmaxf(fmaf(acc1[j][3], sc1[c + 1], sh1[c + 1]), 0.f);
            *(__half2*)&As[row_out * SMEM_ROW_H + c]       = __floats2half2_rn(o00, o01);
            *(__half2*)&As[(row_out + 8) * SMEM_ROW_H + c] = __floats2half2_rn(o10, o11);
        }
    }
    __syncthreads();

    // GEMM2 (4 k-chunks)
    float acc2[2][4];
#pragma unroll
    for (int i = 0; i < 2; i++)
#pragma unroll
        for (int j = 0; j < 4; j++) acc2[i][j] = 0.f;
#pragma unroll
    for (int kc = 0; kc < 4; kc++) {
        unsigned int frag_a[4];
        unsigned int frag_b[4];
        gin_ldsm_a(frag_a, base_as + (unsigned int)((off_a + kc * 16) * 2));
        gin_ldsm_bt(frag_b, base_w2 + (unsigned int)((off_w + kc * 16 * SMEM_ROW_H) * 2));
        gin_mma(acc2[0], frag_a, frag_b[0], frag_b[1]);
        gin_mma(acc2[1], frag_a, frag_b[2], frag_b[3]);
    }

    // epilogue2: +b2, ReLU -> hout (fp16) + Ps (f32 staging)
    {
        int row_half = mma_row * 16 + (lane >> 2);
#pragma unroll
        for (int hb = 0; hb < 2; hb++) {
            int r = row_half + hb * 8;
            int node = node0 + r;
            bool valid = (node < NN);
#pragma unroll
            for (int j = 0; j < 2; j++) {
                int c = mma_col + j * 8 + ((lane & 3) << 1);
                float o0 = valid ? fmaxf(acc2[j][hb * 2 + 0] + b2s[c],     0.f) : 0.f;
                float o1 = valid ? fmaxf(acc2[j][hb * 2 + 1] + b2s[c + 1], 0.f) : 0.f;
                if (valid)
                    *(__half2*)&hout[(size_t)node * 64 + c] = __floats2half2_rn(o0, o1);
                *(float2*)&Ps[r * POOL_ROW_F + c] = make_float2(o0, o1);
            }
        }
    }
    __syncthreads();

    // pooled readout: 8 segments of 8 rows
    {
        int col = tid & 63;
        int seg = tid >> 6;
        int rbeg = seg * 8;
        int cur = bgid[rbeg];
        float run = 0.f;
#pragma unroll
        for (int r = rbeg; r < rbeg + 8; r++) {
            int gid = bgid[r];
            if (gid != cur) {
                atomicAdd(&g_pool[cur * POOLW + pool_off + col], run);
                run = 0.f; cur = gid;
            }
            run += Ps[r * POOL_ROW_F + col];
        }
        atomicAdd(&g_pool[cur * POOLW + pool_off + col], run);
    }
}

// ---------------- layers 2,3: FIN=64 fp16 input; 512 threads, forced 2 blocks/SM ----------------
__global__ void __launch_bounds__(512, 2)
gin_layer_hidden_kernel(const __half* __restrict__ xin,
                        const float* __restrict__ W1, const float* __restrict__ b1,
                        const float* __restrict__ gam, const float* __restrict__ bet,
                        const float* __restrict__ mu, const float* __restrict__ var,
                        const float* __restrict__ W2, const float* __restrict__ b2,
                        const int* __restrict__ batch,
                        __half* __restrict__ hout, int pool_off) {
    __shared__ __align__(16) __half As[64 * SMEM_ROW_H];
    __shared__ __align__(16) __half W1s[64 * SMEM_ROW_H];
    __shared__ __align__(16) __half W2s[64 * SMEM_ROW_H];
    __shared__ float  Ps[64 * POOL_ROW_F];
    __shared__ float  sc1[64], sh1[64], b2s[64];
    __shared__ int    bgid[64];

    int tid = threadIdx.x;
    int node0 = blockIdx.x * 64;
    int warp = tid >> 5, lane = tid & 31;

    for (int idx = tid; idx < 64 * 64; idx += 512) {
        int krow = idx >> 6, ncol = idx & 63;
        W1s[krow * SMEM_ROW_H + ncol] = __float2half(W1[krow * 64 + ncol]);
        W2s[krow * SMEM_ROW_H + ncol] = __float2half(W2[krow * 64 + ncol]);
    }
    if (tid < 64) {
        float bn_scale = gam[tid] * rsqrtf(var[tid] + BN_EPS);
        sc1[tid] = bn_scale;
        sh1[tid] = fmaf(b1[tid] - mu[tid], bn_scale, bet[tid]);
        b2s[tid] = b2[tid];
        int node = node0 + tid;
        bgid[tid] = batch[(node < NN) ? node : (NN - 1)];
    }

    // rowptr warp prefetch: lanes 0..4 load rowptr[warp_base .. warp_base+4]
    int rp_pref = 0;
    {
        int idxp = node0 + warp * 4 + lane;
        if (lane < 5) rp_pref = g_rowptr[(idxp <= NN) ? idxp : NN];
    }

    // gather: half2 per lane, 8-wide edge unroll + index prefetch
    const __half2* xin2 = (const __half2*)xin;
#pragma unroll 1
    for (int i = 0; i < 4; i++) {
        int r = warp * 4 + i;
        int node = node0 + r;
        int s = __shfl_sync(0xffffffffu, rp_pref, i);
        int e = __shfl_sync(0xffffffffu, rp_pref, i + 1);
        float2 acc = make_float2(0.f, 0.f);
        if (node < NN) {
            acc = __half22float2(xin2[node * 32 + lane]);
            int cidx = (s + lane < e) ? g_col[s + lane] : 0;
#pragma unroll 1
            for (int cb = s; cb < e; cb += 32) {
                int cnt = min(32, e - cb);
                int cidx_next = (cb + 32 + lane < e) ? g_col[cb + 32 + lane] : 0;
                int t = 0;
                for (; t + 8 <= cnt; t += 8) {
                    int jj[8];
#pragma unroll
                    for (int q = 0; q < 8; q++) jj[q] = __shfl_sync(0xffffffffu, cidx, t + q);
                    float2 vv[8];
#pragma unroll
                    for (int q = 0; q < 8; q++) vv[q] = __half22float2(xin2[jj[q] * 32 + lane]);
                    acc.x += ((vv[0].x + vv[1].x) + (vv[2].x + vv[3].x)) +
                             ((vv[4].x + vv[5].x) + (vv[6].x + vv[7].x));
                    acc.y += ((vv[0].y + vv[1].y) + (vv[2].y + vv[3].y)) +
                             ((vv[4].y + vv[5].y) + (vv[6].y + vv[7].y));
                }
                for (; t < cnt; t++) {
                    int j = __shfl_sync(0xffffffffu, cidx, t);
                    float2 vv = __half22float2(xin2[j * 32 + lane]);
                    acc.x += vv.x; acc.y += vv.y;
                }
                cidx = cidx_next;
            }
        }
        *(__half2*)&As[r * SMEM_ROW_H + lane * 2] = __floats2half2_rn(acc.x, acc.y);
    }
    __syncthreads();

    int mma_row = warp & 3;
    int mma_col = (warp >> 2) * 16;
    unsigned int base_as = (unsigned int)__cvta_generic_to_shared(As);
    unsigned int base_w1 = (unsigned int)__cvta_generic_to_shared(W1s);
    unsigned int base_w2 = (unsigned int)__cvta_generic_to_shared(W2s);
    int off_a = (mma_row * 16 + (lane & 15)) * SMEM_ROW_H + ((lane >> 4) << 3);
    int off_w = (lane & 15) * SMEM_ROW_H + mma_col + ((lane >> 4) << 3);

    // GEMM1 (4 k-chunks)
    float acc1[2][4];
#pragma unroll
    for (int i = 0; i < 2; i++)
#pragma unroll
        for (int j = 0; j < 4; j++) acc1[i][j] = 0.f;
#pragma unroll
    for (int kc = 0; kc < 4; kc++) {
        unsigned int frag_a[4];
        unsigned int frag_b[4];
        gin_ldsm_a(frag_a, base_as + (unsigned int)((off_a + kc * 16) * 2));
        gin_ldsm_bt(frag_b, base_w1 + (unsigned int)((off_w + kc * 16 * SMEM_ROW_H) * 2));
        gin_mma(acc1[0], frag_a, frag_b[0], frag_b[1]);
        gin_mma(acc1[1], frag_a, frag_b[2], frag_b[3]);
    }
    __syncthreads();

    // epilogue1: BN+ReLU -> As (fp16)
    {
        int row_out = mma_row * 16 + (lane >> 2);
#pragma unroll
        for (int j = 0; j < 2; j++) {
            int c = mma_col + j * 8 + ((lane & 3) << 1);
            float o00 = fmaxf(fmaf(acc1[j][0], sc1[c],     sh1[c]),     0.f);
            float o01 = fmaxf(fmaf(acc1[j][1], sc1[c + 1], sh1[c + 1]), 0.f);
            float o10 = fmaxf(fmaf(acc1[j][2], sc1[c],     sh1[c]),     0.f);
            float o11 = fmaxf(fmaf(acc1[j][3], sc1[c + 1], sh1[c + 1]), 0.f);
            *(__half2*)&As[row_out * SMEM_ROW_H + c]       = __floats2half2_rn(o00, o01);
            *(__half2*)&As[(row_out + 8) * SMEM_ROW_H + c] = __floats2half2_rn(o10, o11);
        }
    }
    __syncthreads();

    // GEMM2
    float acc2[2][4];
#pragma unroll
    for (int i = 0; i < 2; i++)
#pragma unroll
        for (int j = 0; j < 4; j++) acc2[i][j] = 0.f;
#pragma unroll
    for (int kc = 0; kc < 4; kc++) {
        unsigned int frag_a[4];
        unsigned int frag_b[4];
        gin_ldsm_a(frag_a, base_as + (unsigned int)((off_a + kc * 16) * 2));
        gin_ldsm_bt(frag_b, base_w2 + (unsigned int)((off_w + kc * 16 * SMEM_ROW_H) * 2));
        gin_mma(acc2[0], frag_a, frag_b[0], frag_b[1]);
        gin_mma(acc2[1], frag_a, frag_b[2], frag_b[3]);
    }

    // epilogue2: +b2, ReLU -> hout (fp16) + Ps (f32 staging)
    {
        int row_half = mma_row * 16 + (lane >> 2);
#pragma unroll
        for (int hb = 0; hb < 2; hb++) {
            int r = row_half + hb * 8;
            int node = node0 + r;
            bool valid = (node < NN);
#pragma unroll
            for (int j = 0; j < 2; j++) {
                int c = mma_col + j * 8 + ((lane & 3) << 1);
                float o0 = valid ? fmaxf(acc2[j][hb * 2 + 0] + b2s[c],     0.f) : 0.f;
                float o1 = valid ? fmaxf(acc2[j][hb * 2 + 1] + b2s[c + 1], 0.f) : 0.f;
                if (valid)
                    *(__half2*)&hout[(size_t)node * 64 + c] = __floats2half2_rn(o0, o1);
                *(float2*)&Ps[r * POOL_ROW_F + c] = make_float2(o0, o1);
            }
        }
    }
    __syncthreads();

    // pooled readout: 8 segments of 8 rows
    {
        int col = tid & 63;
        int seg = tid >> 6;
        int rbeg = seg * 8;
        int cur = bgid[rbeg];
        float run = 0.f;
#pragma unroll
        for (int r = rbeg; r < rbeg + 8; r++) {
            int gid = bgid[r];
            if (gid != cur) {
                atomicAdd(&g_pool[cur * POOLW + pool_off + col], run);
                run = 0.f; cur = gid;
            }
            run += Ps[r * POOL_ROW_F + col];
        }
        atomicAdd(&g_pool[cur * POOLW + pool_off + col], run);
    }
}

// ---------------- head: fc1(192->192)+ReLU, fc2(192->2), log_softmax ----------------
__global__ void head_kernel(const float* __restrict__ fc1W, const float* __restrict__ fc1b,
                            const float* __restrict__ fc2W, const float* __restrict__ fc2b,
                            float* __restrict__ out) {
    __shared__ float h[POOLW];
    __shared__ float h2[POOLW];
    __shared__ float r0s[6], r1s[6];
    int g = blockIdx.x, t = threadIdx.x;
    h[t] = g_pool[g * POOLW + t];
    __syncthreads();
    float acc = fc1b[t];
#pragma unroll 8
    for (int k = 0; k < POOLW; k++) acc = fmaf(h[k], fc1W[k * POOLW + t], acc);
    h2[t] = fmaxf(acc, 0.f);
    __syncthreads();
    float p0 = h2[t] * fc2W[t * 2 + 0];
    float p1 = h2[t] * fc2W[t * 2 + 1];
#pragma unroll
    for (int o = 16; o > 0; o >>= 1) {
        p0 += __shfl_down_sync(0xffffffffu, p0, o);
        p1 += __shfl_down_sync(0xffffffffu, p1, o);
    }
    if ((t & 31) == 0) { r0s[t >> 5] = p0; r1s[t >> 5] = p1; }
    __syncthreads();
    if (t == 0) {
        float z0 = fc2b[0], z1 = fc2b[1];
#pragma unroll
        for (int w = 0; w < 6; w++) { z0 += r0s[w]; z1 += r1s[w]; }
        float mx = fmaxf(z0, z1);
        float lse = mx + logf(expf(z0 - mx) + expf(z1 - mx));
        out[g * 2 + 0] = z0 - lse;
        out[g * 2 + 1] = z1 - lse;
    }
}

// ---------------- launch ----------------
extern "C" void kernel_launch(void* const* d_in, const int* in_sizes, int n_in,
                              void* d_out, int out_size) {
    const float* x     = (const float*)d_in[0];
    const int*   src   = (const int*)d_in[1];
    const int*   dst   = (const int*)d_in[2];
    const int*   batch = (const int*)d_in[3];

    const float* c1p[8]; for (int i = 0; i < 8; i++) c1p[i] = (const float*)d_in[4 + i];
    const float* c2p[8]; for (int i = 0; i < 8; i++) c2p[i] = (const float*)d_in[12 + i];
    const float* c3p[8]; for (int i = 0; i < 8; i++) c3p[i] = (const float*)d_in[20 + i];
    const float* fc1W = (const float*)d_in[28];
    const float* fc1b = (const float*)d_in[29];
    const float* fc2W = (const float*)d_in[30];
    const float* fc2b = (const float*)d_in[31];
    float* out = (float*)d_out;

    __half *hA_p, *hB_p;
    cudaGetSymbolAddress((void**)&hA_p, g_hA);
    cudaGetSymbolAddress((void**)&hB_p, g_hB);

    const int TPB = 256;
    int blkN = (NN + TPB - 1) / TPB;                 // 391
    int blkE8 = (EE / 8 + TPB - 1) / TPB;            // 1563 (8 edges/thread)
    int blkM = (NN + 63) / 64;                       // 1563

    // CSR build (hist computes per-edge rank; scatter is atomic-free)
    init_zero_kernel<<<blkN, TPB>>>();
    hist_kernel<<<blkE8, TPB>>>(dst);
    scan_block_kernel<<<NBLK, 256>>>();
    scan_bsum_kernel<<<1, 512>>>();
    scan_add_kernel<<<NBLK, 256>>>();
    scatter_kernel<<<blkE8, TPB>>>(src, dst);

    // fused GIN layers (gather + tensor-core MLP + pooling), 512 threads, 2 blocks/SM
    gin_layer_first_kernel<<<blkM, 512>>>(x, c1p[0], c1p[1], c1p[2], c1p[3], c1p[4],
                                          c1p[5], c1p[6], c1p[7], batch, hA_p, 0);
    gin_layer_hidden_kernel<<<blkM, 512>>>(hA_p, c2p[0], c2p[1], c2p[2], c2p[3], c2p[4],
                                           c2p[5], c2p[6], c2p[7], batch, hB_p, 64);
    gin_layer_hidden_kernel<<<blkM, 512>>>(hB_p, c3p[0], c3p[1], c3p[2], c3p[3], c3p[4],
                                           c3p[5], c3p[6], c3p[7], batch, hA_p, 128);

    // readout head
    head_kernel<<<GG, POOLW>>>(fc1W, fc1b, fc2W, fc2b, out);
}

// round 16
// speedup vs baseline: 1.1550x; 1.1550x over previous
#include <cuda_runtime.h>
#include <cuda_fp16.h>
#include <stdint.h>
#include <math.h>

#define NN 100000
#define EE 3200000
#define FF 13
#define HH 64
#define GG 512
#define POOLW 192
#define BN_EPS 1e-5f
#define NBLK 391   /* ceil(NN/256) */

// ---------------- scratch (device globals: allocation-free) ----------------
__device__ int    g_deg[NN];
__device__ int    g_rowptr[NN + 1];
__device__ int    g_rank[EE];
__device__ int    g_col[EE];
__device__ int    g_bsum[512];
__device__ __align__(16) __half g_hA[NN * 64];
__device__ __align__(16) __half g_hB[NN * 64];
__device__ __align__(16) __half g_agg[NN * 64];
__device__ float  g_pool[GG * POOLW];

// ---------------- PTX helpers ----------------
__device__ __forceinline__ void gin_ldsm_a(unsigned int* frag_out4, unsigned int smem_addr_u32) {
    asm volatile("ldmatrix.sync.aligned.m8n8.x4.shared.b16 {%0,%1,%2,%3}, [%4];"
                 : "=r"(frag_out4[0]), "=r"(frag_out4[1]),
                   "=r"(frag_out4[2]), "=r"(frag_out4[3])
                 : "r"(smem_addr_u32));
}

__device__ __forceinline__ void gin_ldsm_bt(unsigned int* frag_out4, unsigned int smem_addr_u32) {
    asm volatile("ldmatrix.sync.aligned.m8n8.x4.trans.shared.b16 {%0,%1,%2,%3}, [%4];"
                 : "=r"(frag_out4[0]), "=r"(frag_out4[1]),
                   "=r"(frag_out4[2]), "=r"(frag_out4[3])
                 : "r"(smem_addr_u32));
}

__device__ __forceinline__ void gin_mma(float* acc_inout4, const unsigned int* frag_a4,
                                        unsigned int frag_b_first, unsigned int frag_b_second) {
    asm volatile(
        "mma.sync.aligned.m16n8k16.row.col.f32.f16.f16.f32 "
        "{%0,%1,%2,%3}, {%4,%5,%6,%7}, {%8,%9}, {%0,%1,%2,%3};"
        : "+f"(acc_inout4[0]), "+f"(acc_inout4[1]),
          "+f"(acc_inout4[2]), "+f"(acc_inout4[3])
        : "r"(frag_a4[0]), "r"(frag_a4[1]), "r"(frag_a4[2]), "r"(frag_a4[3]),
          "r"(frag_b_first), "r"(frag_b_second));
}

// ---------------- CSR build ----------------
__global__ void init_zero_kernel() {
    int i = blockIdx.x * blockDim.x + threadIdx.x;
    if (i < NN) g_deg[i] = 0;
    if (i < GG * POOLW) g_pool[i] = 0.f;
}

// hist + rank: the atomic's return value is this edge's slot within its dst row.
__global__ void hist_kernel(const int* __restrict__ dst) {
    int i = (blockIdx.x * blockDim.x + threadIdx.x) * 8;
    if (i < EE) {  // EE % 8 == 0
        int4 dva = *(const int4*)&dst[i];
        int4 dvb = *(const int4*)&dst[i + 4];
        int r0 = atomicAdd(&g_deg[dva.x], 1);
        int r1 = atomicAdd(&g_deg[dva.y], 1);
        int r2 = atomicAdd(&g_deg[dva.z], 1);
        int r3 = atomicAdd(&g_deg[dva.w], 1);
        int r4 = atomicAdd(&g_deg[dvb.x], 1);
        int r5 = atomicAdd(&g_deg[dvb.y], 1);
        int r6 = atomicAdd(&g_deg[dvb.z], 1);
        int r7 = atomicAdd(&g_deg[dvb.w], 1);
        *(int4*)&g_rank[i]     = make_int4(r0, r1, r2, r3);
        *(int4*)&g_rank[i + 4] = make_int4(r4, r5, r6, r7);
    }
}

// Hierarchical scan, stage 1: per-block (256-wide) exclusive scan + block sums
__global__ void scan_block_kernel() {
    __shared__ int wsum[8];
    int tid = threadIdx.x;
    int i = blockIdx.x * 256 + tid;
    int v = (i < NN) ? g_deg[i] : 0;
    int x = v;
#pragma unroll
    for (int o = 1; o < 32; o <<= 1) {
        int y = __shfl_up_sync(0xffffffffu, x, o);
        if ((tid & 31) >= o) x += y;
    }
    if ((tid & 31) == 31) wsum[tid >> 5] = x;
    __syncthreads();
    if (tid == 0) {
        int run = 0;
#pragma unroll
        for (int w = 0; w < 8; w++) { int tmpv = wsum[w]; wsum[w] = run; run += tmpv; }
        g_bsum[blockIdx.x] = run;
    }
    __syncthreads();
    if (i < NN) g_rowptr[i] = x - v + wsum[tid >> 5];
}

// Stage 2: single-block exclusive scan over the 391 block sums (in place)
__global__ void scan_bsum_kernel() {
    __shared__ int wsum[16];
    int tid = threadIdx.x;   // 512 threads
    int v = (tid < NBLK) ? g_bsum[tid] : 0;
    int x = v;
#pragma unroll
    for (int o = 1; o < 32; o <<= 1) {
        int y = __shfl_up_sync(0xffffffffu, x, o);
        if ((tid & 31) >= o) x += y;
    }
    if ((tid & 31) == 31) wsum[tid >> 5] = x;
    __syncthreads();
    if (tid == 0) {
        int run = 0;
#pragma unroll
        for (int w = 0; w < 16; w++) { int tmpv = wsum[w]; wsum[w] = run; run += tmpv; }
    }
    __syncthreads();
    if (tid < NBLK) g_bsum[tid] = x - v + wsum[tid >> 5];
}

// Stage 3: add block offsets, set rowptr[NN]
__global__ void scan_add_kernel() {
    int tid = threadIdx.x;
    int i = blockIdx.x * 256 + tid;
    if (i < NN) g_rowptr[i] = g_rowptr[i] + g_bsum[blockIdx.x];
    if (i == 0) g_rowptr[NN] = EE;
}

// scatter with precomputed ranks: NO atomics — pure load/store with deep MLP.
__global__ void scatter_kernel(const int* __restrict__ src, const int* __restrict__ dst) {
    int i = (blockIdx.x * blockDim.x + threadIdx.x) * 8;
    if (i < EE) {
        int4 dva = *(const int4*)&dst[i];
        int4 dvb = *(const int4*)&dst[i + 4];
        int4 sva = *(const int4*)&src[i];
        int4 svb = *(const int4*)&src[i + 4];
        int4 rva = *(const int4*)&g_rank[i];
        int4 rvb = *(const int4*)&g_rank[i + 4];
        g_col[g_rowptr[dva.x] + rva.x] = sva.x;
        g_col[g_rowptr[dva.y] + rva.y] = sva.y;
        g_col[g_rowptr[dva.z] + rva.z] = sva.z;
        g_col[g_rowptr[dva.w] + rva.w] = sva.w;
        g_col[g_rowptr[dvb.x] + rvb.x] = svb.x;
        g_col[g_rowptr[dvb.y] + rvb.y] = svb.y;
        g_col[g_rowptr[dvb.z] + rvb.z] = svb.z;
        g_col[g_rowptr[dvb.w] + rvb.w] = svb.w;
    }
}

// ---------------- standalone hidden-layer gather: warp per node, no smem ----------------
// High occupancy (no MMA regs, no smem) to hide L2 gather latency with TLP.
__global__ void __launch_bounds__(256)
gather_hidden_kernel(const __half* __restrict__ xin) {
    int warp = (blockIdx.x * 256 + threadIdx.x) >> 5;
    int lane = threadIdx.x & 31;
    int node = warp;
    if (node >= NN) return;
    const __half2* xin2 = (const __half2*)xin;
    float2 acc = __half22float2(xin2[node * 32 + lane]);
    int s = g_rowptr[node], e = g_rowptr[node + 1];
    int cidx = (s + lane < e) ? g_col[s + lane] : 0;
#pragma unroll 1
    for (int cb = s; cb < e; cb += 32) {
        int cnt = min(32, e - cb);
        int cidx_next = (cb + 32 + lane < e) ? g_col[cb + 32 + lane] : 0;
        int t = 0;
        for (; t + 8 <= cnt; t += 8) {
            int jj[8];
#pragma unroll
            for (int q = 0; q < 8; q++) jj[q] = __shfl_sync(0xffffffffu, cidx, t + q);
            float2 vv[8];
#pragma unroll
            for (int q = 0; q < 8; q++) vv[q] = __half22float2(xin2[jj[q] * 32 + lane]);
            acc.x += ((vv[0].x + vv[1].x) + (vv[2].x + vv[3].x)) +
                     ((vv[4].x + vv[5].x) + (vv[6].x + vv[7].x));
            acc.y += ((vv[0].y + vv[1].y) + (vv[2].y + vv[3].y)) +
                     ((vv[4].y + vv[5].y) + (vv[6].y + vv[7].y));
        }
        for (; t < cnt; t++) {
            int j = __shfl_sync(0xffffffffu, cidx, t);
            float2 vv = __half22float2(xin2[j * 32 + lane]);
            acc.x += vv.x; acc.y += vv.y;
        }
        cidx = cidx_next;
    }
    ((__half2*)g_agg)[node * 32 + lane] = __floats2half2_rn(acc.x, acc.y);
}

// smem layout constants
#define SMEM_ROW_H 72   /* half elements per row (144B): ldmatrix conflict-free */
#define POOL_ROW_F 68   /* float elements per row of pool staging */

// ---------------- layer 1: FIN=13 fp32 input; fused gather+MLP (round-12 form) ----------------
__global__ void __launch_bounds__(512)
gin_layer_first_kernel(const float* __restrict__ xin,
                       const float* __restrict__ W1, const float* __restrict__ b1,
                       const float* __restrict__ gam, const float* __restrict__ bet,
                       const float* __restrict__ mu, const float* __restrict__ var,
                       const float* __restrict__ W2, const float* __restrict__ b2,
                       const int* __restrict__ batch,
                       __half* __restrict__ hout, int pool_off) {
    __shared__ __align__(16) __half As[64 * SMEM_ROW_H];
    __shared__ __align__(16) __half W1s[64 * SMEM_ROW_H];
    __shared__ __align__(16) __half W2s[64 * SMEM_ROW_H];
    __shared__ float  Ps[64 * POOL_ROW_F];
    __shared__ float  sc1[64], sh1[64], b2s[64];
    __shared__ int    bgid[64];

    int tid = threadIdx.x;
    int node0 = blockIdx.x * 64;
    int warp = tid >> 5, lane = tid & 31;

    for (int idx = tid; idx < 16 * 64; idx += 512) {
        int krow = idx >> 6, ncol = idx & 63;
        W1s[krow * SMEM_ROW_H + ncol] = __float2half((krow < FF) ? W1[krow * 64 + ncol] : 0.f);
    }
    for (int idx = tid; idx < 64 * 64; idx += 512) {
        int krow = idx >> 6, ncol = idx & 63;
        W2s[krow * SMEM_ROW_H + ncol] = __float2half(W2[krow * 64 + ncol]);
    }
    if (tid < 64) {
        float bn_scale = gam[tid] * rsqrtf(var[tid] + BN_EPS);
        sc1[tid] = bn_scale;
        sh1[tid] = fmaf(b1[tid] - mu[tid], bn_scale, bet[tid]);
        b2s[tid] = b2[tid];
        int node = node0 + tid;
        bgid[tid] = batch[(node < NN) ? node : (NN - 1)];
    }

    // gather: 8-wide edge unroll + index prefetch
#pragma unroll 1
    for (int i = 0; i < 4; i++) {
        int r = warp * 4 + i;
        int node = node0 + r;
        float acc = 0.f;
        if (node < NN && lane < FF) acc = xin[node * FF + lane];
        if (node < NN) {
            int s = g_rowptr[node], e = g_rowptr[node + 1];
            int cidx = (s + lane < e) ? g_col[s + lane] : 0;
#pragma unroll 1
            for (int cb = s; cb < e; cb += 32) {
                int cnt = min(32, e - cb);
                int cidx_next = (cb + 32 + lane < e) ? g_col[cb + 32 + lane] : 0;
                int t = 0;
                for (; t + 8 <= cnt; t += 8) {
                    int jj[8];
#pragma unroll
                    for (int q = 0; q < 8; q++) jj[q] = __shfl_sync(0xffffffffu, cidx, t + q);
                    if (lane < FF) {
                        float vv[8];
#pragma unroll
                        for (int q = 0; q < 8; q++) vv[q] = xin[jj[q] * FF + lane];
                        acc += ((vv[0] + vv[1]) + (vv[2] + vv[3])) +
                               ((vv[4] + vv[5]) + (vv[6] + vv[7]));
                    }
                }
                for (; t < cnt; t++) {
                    int j = __shfl_sync(0xffffffffu, cidx, t);
                    if (lane < FF) acc += xin[j * FF + lane];
                }
                cidx = cidx_next;
            }
        }
        if (lane < 16) As[r * SMEM_ROW_H + lane] = __float2half((lane < FF) ? acc : 0.f);
    }
    __syncthreads();

    int mma_row = warp & 3;            // rows (warp&3)*16..+15
    int mma_col = (warp >> 2) * 16;    // 16 cols per warp
    unsigned int base_as = (unsigned int)__cvta_generic_to_shared(As);
    unsigned int base_w1 = (unsigned int)__cvta_generic_to_shared(W1s);
    unsigned int base_w2 = (unsigned int)__cvta_generic_to_shared(W2s);
    int off_a = (mma_row * 16 + (lane & 15)) * SMEM_ROW_H + ((lane >> 4) << 3);
    int off_w = (lane & 15) * SMEM_ROW_H + mma_col + ((lane >> 4) << 3);

    // GEMM1 (KPAD=16 -> single k-chunk)
    float acc1[2][4];
#pragma unroll
    for (int i = 0; i < 2; i++)
#pragma unroll
        for (int j = 0; j < 4; j++) acc1[i][j] = 0.f;
    {
        unsigned int frag_a[4];
        unsigned int frag_b[4];
        gin_ldsm_a(frag_a, base_as + (unsigned int)(off_a * 2));
        gin_ldsm_bt(frag_b, base_w1 + (unsigned int)(off_w * 2));
        gin_mma(acc1[0], frag_a, frag_b[0], frag_b[1]);
        gin_mma(acc1[1], frag_a, frag_b[2], frag_b[3]);
    }
    __syncthreads();

    // epilogue1: BN+ReLU -> As (fp16)
    {
        int row_out = mma_row * 16 + (lane >> 2);
#pragma unroll
        for (int j = 0; j < 2; j++) {
            int c = mma_col + j * 8 + ((lane & 3) << 1);
            float o00 = fmaxf(fmaf(acc1[j][0], sc1[c],     sh1[c]),     0.f);
            float o01 = fmaxf(fmaf(acc1[j][1], sc1[c + 1], sh1[c + 1]), 0.f);
            float o10 = fmaxf(fmaf(acc1[j][2], sc1[c],     sh1[c]),     0.f);
            float o11 = fmaxf(fmaf(acc1[j][3], sc1[c + 1], sh1[c + 1]), 0.f);
            *(__half2*)&As[row_out * SMEM_ROW_H + c]       = __floats2half2_rn(o00, o01);
            *(__half2*)&As[(row_out + 8) * SMEM_ROW_H + c] = __floats2half2_rn(o10, o11);
        }
    }
    __syncthreads();

    // GEMM2 (4 k-chunks)
    float acc2[2][4];
#pragma unroll
    for (int i = 0; i < 2; i++)
#pragma unroll
        for (int j = 0; j < 4; j++) acc2[i][j] = 0.f;
#pragma unroll
    for (int kc = 0; kc < 4; kc++) {
        unsigned int frag_a[4];
        unsigned int frag_b[4];
        gin_ldsm_a(frag_a, base_as + (unsigned int)((off_a + kc * 16) * 2));
        gin_ldsm_bt(frag_b, base_w2 + (unsigned int)((off_w + kc * 16 * SMEM_ROW_H) * 2));
        gin_mma(acc2[0], frag_a, frag_b[0], frag_b[1]);
        gin_mma(acc2[1], frag_a, frag_b[2], frag_b[3]);
    }

    // epilogue2: +b2, ReLU -> hout (fp16) + Ps (f32 staging)
    {
        int row_half = mma_row * 16 + (lane >> 2);
#pragma unroll
        for (int hb = 0; hb < 2; hb++) {
            int r = row_half + hb * 8;
            int node = node0 + r;
            bool valid = (node < NN);
#pragma unroll
            for (int j = 0; j < 2; j++) {
                int c = mma_col + j * 8 + ((lane & 3) << 1);
                float o0 = valid ? fmaxf(acc2[j][hb * 2 + 0] + b2s[c],     0.f) : 0.f;
                float o1 = valid ? fmaxf(acc2[j][hb * 2 + 1] + b2s[c + 1], 0.f) : 0.f;
                if (valid)
                    *(__half2*)&hout[(size_t)node * 64 + c] = __floats2half2_rn(o0, o1);
                *(float2*)&Ps[r * POOL_ROW_F + c] = make_float2(o0, o1);
            }
        }
    }
    __syncthreads();

    // pooled readout: 8 segments of 8 rows
    {
        int col = tid & 63;
        int seg = tid >> 6;
        int rbeg = seg * 8;
        int cur = bgid[rbeg];
        float run = 0.f;
#pragma unroll
        for (int r = rbeg; r < rbeg + 8; r++) {
            int gid = bgid[r];
            if (gid != cur) {
                atomicAdd(&g_pool[cur * POOLW + pool_off + col], run);
                run = 0.f; cur = gid;
            }
            run += Ps[r * POOL_ROW_F + col];
        }
        atomicAdd(&g_pool[cur * POOLW + pool_off + col], run);
    }
}

// ---------------- hidden-layer MLP: reads pre-gathered g_agg (coalesced) ----------------
__global__ void __launch_bounds__(512)
mlp_hidden_kernel(const float* __restrict__ W1, const float* __restrict__ b1,
                  const float* __restrict__ gam, const float* __restrict__ bet,
                  const float* __restrict__ mu, const float* __restrict__ var,
                  const float* __restrict__ W2, const float* __restrict__ b2,
                  const int* __restrict__ batch,
                  __half* __restrict__ hout, int pool_off) {
    __shared__ __align__(16) __half As[64 * SMEM_ROW_H];
    __shared__ __align__(16) __half W1s[64 * SMEM_ROW_H];
    __shared__ __align__(16) __half W2s[64 * SMEM_ROW_H];
    __shared__ float  Ps[64 * POOL_ROW_F];
    __shared__ float  sc1[64], sh1[64], b2s[64];
    __shared__ int    bgid[64];

    int tid = threadIdx.x;
    int node0 = blockIdx.x * 64;
    int warp = tid >> 5, lane = tid & 31;

    for (int idx = tid; idx < 64 * 64; idx += 512) {
        int krow = idx >> 6, ncol = idx & 63;
        W1s[krow * SMEM_ROW_H + ncol] = __float2half(W1[krow * 64 + ncol]);
        W2s[krow * SMEM_ROW_H + ncol] = __float2half(W2[krow * 64 + ncol]);
    }
    if (tid < 64) {
        float bn_scale = gam[tid] * rsqrtf(var[tid] + BN_EPS);
        sc1[tid] = bn_scale;
        sh1[tid] = fmaf(b1[tid] - mu[tid], bn_scale, bet[tid]);
        b2s[tid] = b2[tid];
        int node = node0 + tid;
        bgid[tid] = batch[(node < NN) ? node : (NN - 1)];
    }

    // Load A tile from g_agg: thread t -> row t>>3, 16B chunk t&7 (one pass, coalesced)
    {
        int row = tid >> 3;
        int chk = tid & 7;
        int node = node0 + row;
        uint4 rv = make_uint4(0u, 0u, 0u, 0u);
        if (node < NN) rv = ((const uint4*)g_agg)[(size_t)node * 8 + chk];
        *(uint4*)&As[row * SMEM_ROW_H + chk * 8] = rv;
    }
    __syncthreads();

    int mma_row = warp & 3;
    int mma_col = (warp >> 2) * 16;
    unsigned int base_as = (unsigned int)__cvta_generic_to_shared(As);
    unsigned int base_w1 = (unsigned int)__cvta_generic_to_shared(W1s);
    unsigned int base_w2 = (unsigned int)__cvta_generic_to_shared(W2s);
    int off_a = (mma_row * 16 + (lane & 15)) * SMEM_ROW_H + ((lane >> 4) << 3);
    int off_w = (lane & 15) * SMEM_ROW_H + mma_col + ((lane >> 4) << 3);

    // GEMM1 (4 k-chunks)
    float acc1[2][4];
#pragma unroll
    for (int i = 0; i < 2; i++)
#pragma unroll
        for (int j = 0; j < 4; j++) acc1[i][j] = 0.f;
#pragma unroll
    for (int kc = 0; kc < 4; kc++) {
        unsigned int frag_a[4];
        unsigned int frag_b[4];
        gin_ldsm_a(frag_a, base_as + (unsigned int)((off_a + kc * 16) * 2));
        gin_ldsm_bt(frag_b, base_w1 + (unsigned int)((off_w + kc * 16 * SMEM_ROW_H) * 2));
        gin_mma(acc1[0], frag_a, frag_b[0], frag_b[1]);
        gin_mma(acc1[1], frag_a, frag_b[2], frag_b[3]);
    }
    __syncthreads();

    // epilogue1: BN+ReLU -> As (fp16)
    {
        int row_out = mma_row * 16 + (lane >> 2);
#pragma unroll
        for (int j = 0; j < 2; j++) {
            int c = mma_col + j * 8 + ((lane & 3) << 1);
            float o00 = fmaxf(fmaf(acc1[j][0], sc1[c],     sh1[c]),     0.f);
            float o01 = fmaxf(fmaf(acc1[j][1], sc1[c + 1], sh1[c + 1]), 0.f);
            float o10 = fmaxf(fmaf(acc1[j][2], sc1[c],     sh1[c]),     0.f);
            float o11 = fmaxf(fmaf(acc1[j][3], sc1[c + 1], sh1[c + 1]), 0.f);
            *(__half2*)&As[row_out * SMEM_ROW_H + c]       = __floats2half2_rn(o00, o01);
            *(__half2*)&As[(row_out + 8) * SMEM_ROW_H + c] = __floats2half2_rn(o10, o11);
        }
    }
    __syncthreads();

    // GEMM2
    float acc2[2][4];
#pragma unroll
    for (int i = 0; i < 2; i++)
#pragma unroll
        for (int j = 0; j < 4; j++) acc2[i][j] = 0.f;
#pragma unroll
    for (int kc = 0; kc < 4; kc++) {
        unsigned int frag_a[4];
        unsigned int frag_b[4];
        gin_ldsm_a(frag_a, base_as + (unsigned int)((off_a + kc * 16) * 2));
        gin_ldsm_bt(frag_b, base_w2 + (unsigned int)((off_w + kc * 16 * SMEM_ROW_H) * 2));
        gin_mma(acc2[0], frag_a, frag_b[0], frag_b[1]);
        gin_mma(acc2[1], frag_a, frag_b[2], frag_b[3]);
    }

    // epilogue2: +b2, ReLU -> hout (fp16) + Ps (f32 staging)
    {
        int row_half = mma_row * 16 + (lane >> 2);
#pragma unroll
        for (int hb = 0; hb < 2; hb++) {
            int r = row_half + hb * 8;
            int node = node0 + r;
            bool valid = (node < NN);
#pragma unroll
            for (int j = 0; j < 2; j++) {
                int c = mma_col + j * 8 + ((lane & 3) << 1);
                float o0 = valid ? fmaxf(acc2[j][hb * 2 + 0] + b2s[c],     0.f) : 0.f;
                float o1 = valid ? fmaxf(acc2[j][hb * 2 + 1] + b2s[c + 1], 0.f) : 0.f;
                if (valid)
                    *(__half2*)&hout[(size_t)node * 64 + c] = __floats2half2_rn(o0, o1);
                *(float2*)&Ps[r * POOL_ROW_F + c] = make_float2(o0, o1);
            }
        }
    }
    __syncthreads();

    // pooled readout: 8 segments of 8 rows
    {
        int col = tid & 63;
        int seg = tid >> 6;
        int rbeg = seg * 8;
        int cur = bgid[rbeg];
        float run = 0.f;
#pragma unroll
        for (int r = rbeg; r < rbeg + 8; r++) {
            int gid = bgid[r];
            if (gid != cur) {
                atomicAdd(&g_pool[cur * POOLW + pool_off + col], run);
                run = 0.f; cur = gid;
            }
            run += Ps[r * POOL_ROW_F + col];
        }
        atomicAdd(&g_pool[cur * POOLW + pool_off + col], run);
    }
}

// ---------------- head: fc1(192->192)+ReLU, fc2(192->2), log_softmax ----------------
__global__ void head_kernel(const float* __restrict__ fc1W, const float* __restrict__ fc1b,
                            const float* __restrict__ fc2W, const float* __restrict__ fc2b,
                            float* __restrict__ out) {
    __shared__ float h[POOLW];
    __shared__ float h2[POOLW];
    __shared__ float r0s[6], r1s[6];
    int g = blockIdx.x, t = threadIdx.x;
    h[t] = g_pool[g * POOLW + t];
    __syncthreads();
    float acc = fc1b[t];
#pragma unroll 8
    for (int k = 0; k < POOLW; k++) acc = fmaf(h[k], fc1W[k * POOLW + t], acc);
    h2[t] = fmaxf(acc, 0.f);
    __syncthreads();
    float p0 = h2[t] * fc2W[t * 2 + 0];
    float p1 = h2[t] * fc2W[t * 2 + 1];
#pragma unroll
    for (int o = 16; o > 0; o >>= 1) {
        p0 += __shfl_down_sync(0xffffffffu, p0, o);
        p1 += __shfl_down_sync(0xffffffffu, p1, o);
    }
    if ((t & 31) == 0) { r0s[t >> 5] = p0; r1s[t >> 5] = p1; }
    __syncthreads();
    if (t == 0) {
        float z0 = fc2b[0], z1 = fc2b[1];
#pragma unroll
        for (int w = 0; w < 6; w++) { z0 += r0s[w]; z1 += r1s[w]; }
        float mx = fmaxf(z0, z1);
        float lse = mx + logf(expf(z0 - mx) + expf(z1 - mx));
        out[g * 2 + 0] = z0 - lse;
        out[g * 2 + 1] = z1 - lse;
    }
}

// ---------------- launch ----------------
extern "C" void kernel_launch(void* const* d_in, const int* in_sizes, int n_in,
                              void* d_out, int out_size) {
    const float* x     = (const float*)d_in[0];
    const int*   src   = (const int*)d_in[1];
    const int*   dst   = (const int*)d_in[2];
    const int*   batch = (const int*)d_in[3];

    const float* c1p[8]; for (int i = 0; i < 8; i++) c1p[i] = (const float*)d_in[4 + i];
    const float* c2p[8]; for (int i = 0; i < 8; i++) c2p[i] = (const float*)d_in[12 + i];
    const float* c3p[8]; for (int i = 0; i < 8; i++) c3p[i] = (const float*)d_in[20 + i];
    const float* fc1W = (const float*)d_in[28];
    const float* fc1b = (const float*)d_in[29];
    const float* fc2W = (const float*)d_in[30];
    const float* fc2b = (const float*)d_in[31];
    float* out = (float*)d_out;

    __half *hA_p, *hB_p;
    cudaGetSymbolAddress((void**)&hA_p, g_hA);
    cudaGetSymbolAddress((void**)&hB_p, g_hB);

    const int TPB = 256;
    int blkN = (NN + TPB - 1) / TPB;                 // 391
    int blkE8 = (EE / 8 + TPB - 1) / TPB;            // 1563 (8 edges/thread)
    int blkM = (NN + 63) / 64;                       // 1563
    int blkG = (NN * 32 + TPB - 1) / TPB;            // 12500 (warp per node)

    // CSR build (hist computes per-edge rank; scatter is atomic-free)
    init_zero_kernel<<<blkN, TPB>>>();
    hist_kernel<<<blkE8, TPB>>>(dst);
    scan_block_kernel<<<NBLK, 256>>>();
    scan_bsum_kernel<<<1, 512>>>();
    scan_add_kernel<<<NBLK, 256>>>();
    scatter_kernel<<<blkE8, TPB>>>(src, dst);

    // layer 1: fused (fp32 13-wide gather is cheap)
    gin_layer_first_kernel<<<blkM, 512>>>(x, c1p[0], c1p[1], c1p[2], c1p[3], c1p[4],
                                          c1p[5], c1p[6], c1p[7], batch, hA_p, 0);
    // layer 2: high-occupancy gather, then coalesced MLP
    gather_hidden_kernel<<<blkG, TPB>>>(hA_p);
    mlp_hidden_kernel<<<blkM, 512>>>(c2p[0], c2p[1], c2p[2], c2p[3], c2p[4],
                                     c2p[5], c2p[6], c2p[7], batch, hB_p, 64);
    // layer 3
    gather_hidden_kernel<<<blkG, TPB>>>(hB_p);
    mlp_hidden_kernel<<<blkM, 512>>>(c3p[0], c3p[1], c3p[2], c3p[3], c3p[4],
                                     c3p[5], c3p[6], c3p[7], batch, hA_p, 128);

    // readout head
    head_kernel<<<GG, POOLW>>>(fc1W, fc1b, fc2W, fc2b, out);
}

// round 17
// speedup vs baseline: 1.2094x; 1.0472x over previous
#include <cuda_runtime.h>
#include <cuda_fp16.h>
#include <stdint.h>
#include <math.h>

#define NN 100000
#define EE 3200000
#define FF 13
#define HH 64
#define GG 512
#define POOLW 192
#define BN_EPS 1e-5f
#define NBLK 391   /* ceil(NN/256) */

// ---------------- scratch (device globals: allocation-free) ----------------
__device__ int    g_deg[NN];
__device__ int    g_rowptr[NN + 1];
__device__ int    g_rank[EE];
__device__ int    g_col[EE];
__device__ int    g_bsum[512];
__device__ __align__(16) __half g_hA[NN * 64];
__device__ __align__(16) __half g_hB[NN * 64];
__device__ __align__(16) __half g_agg[NN * 64];
__device__ float  g_pool[GG * POOLW];

// ---------------- PTX helpers ----------------
__device__ __forceinline__ void gin_ldsm_a(unsigned int* frag_out4, unsigned int smem_addr_u32) {
    asm volatile("ldmatrix.sync.aligned.m8n8.x4.shared.b16 {%0,%1,%2,%3}, [%4];"
                 : "=r"(frag_out4[0]), "=r"(frag_out4[1]),
                   "=r"(frag_out4[2]), "=r"(frag_out4[3])
                 : "r"(smem_addr_u32));
}

__device__ __forceinline__ void gin_ldsm_bt(unsigned int* frag_out4, unsigned int smem_addr_u32) {
    asm volatile("ldmatrix.sync.aligned.m8n8.x4.trans.shared.b16 {%0,%1,%2,%3}, [%4];"
                 : "=r"(frag_out4[0]), "=r"(frag_out4[1]),
                   "=r"(frag_out4[2]), "=r"(frag_out4[3])
                 : "r"(smem_addr_u32));
}

__device__ __forceinline__ void gin_mma(float* acc_inout4, const unsigned int* frag_a4,
                                        unsigned int frag_b_first, unsigned int frag_b_second) {
    asm volatile(
        "mma.sync.aligned.m16n8k16.row.col.f32.f16.f16.f32 "
        "{%0,%1,%2,%3}, {%4,%5,%6,%7}, {%8,%9}, {%0,%1,%2,%3};"
        : "+f"(acc_inout4[0]), "+f"(acc_inout4[1]),
          "+f"(acc_inout4[2]), "+f"(acc_inout4[3])
        : "r"(frag_a4[0]), "r"(frag_a4[1]), "r"(frag_a4[2]), "r"(frag_a4[3]),
          "r"(frag_b_first), "r"(frag_b_second));
}

// ---------------- CSR build ----------------
__global__ void init_zero_kernel() {
    int i = blockIdx.x * blockDim.x + threadIdx.x;
    if (i < NN) g_deg[i] = 0;
    if (i < GG * POOLW) g_pool[i] = 0.f;
}

// hist + rank: the atomic's return value is this edge's slot within its dst row.
__global__ void hist_kernel(const int* __restrict__ dst) {
    int i = (blockIdx.x * blockDim.x + threadIdx.x) * 8;
    if (i < EE) {  // EE % 8 == 0
        int4 dva = *(const int4*)&dst[i];
        int4 dvb = *(const int4*)&dst[i + 4];
        int r0 = atomicAdd(&g_deg[dva.x], 1);
        int r1 = atomicAdd(&g_deg[dva.y], 1);
        int r2 = atomicAdd(&g_deg[dva.z], 1);
        int r3 = atomicAdd(&g_deg[dva.w], 1);
        int r4 = atomicAdd(&g_deg[dvb.x], 1);
        int r5 = atomicAdd(&g_deg[dvb.y], 1);
        int r6 = atomicAdd(&g_deg[dvb.z], 1);
        int r7 = atomicAdd(&g_deg[dvb.w], 1);
        *(int4*)&g_rank[i]     = make_int4(r0, r1, r2, r3);
        *(int4*)&g_rank[i + 4] = make_int4(r4, r5, r6, r7);
    }
}

// Hierarchical scan, stage 1: per-block (256-wide) exclusive scan + block sums
__global__ void scan_block_kernel() {
    __shared__ int wsum[8];
    int tid = threadIdx.x;
    int i = blockIdx.x * 256 + tid;
    int v = (i < NN) ? g_deg[i] : 0;
    int x = v;
#pragma unroll
    for (int o = 1; o < 32; o <<= 1) {
        int y = __shfl_up_sync(0xffffffffu, x, o);
        if ((tid & 31) >= o) x += y;
    }
    if ((tid & 31) == 31) wsum[tid >> 5] = x;
    __syncthreads();
    if (tid == 0) {
        int run = 0;
#pragma unroll
        for (int w = 0; w < 8; w++) { int tmpv = wsum[w]; wsum[w] = run; run += tmpv; }
        g_bsum[blockIdx.x] = run;
    }
    __syncthreads();
    if (i < NN) g_rowptr[i] = x - v + wsum[tid >> 5];
}

// Stage 2: single-block exclusive scan over the 391 block sums (in place)
__global__ void scan_bsum_kernel() {
    __shared__ int wsum[16];
    int tid = threadIdx.x;   // 512 threads
    int v = (tid < NBLK) ? g_bsum[tid] : 0;
    int x = v;
#pragma unroll
    for (int o = 1; o < 32; o <<= 1) {
        int y = __shfl_up_sync(0xffffffffu, x, o);
        if ((tid & 31) >= o) x += y;
    }
    if ((tid & 31) == 31) wsum[tid >> 5] = x;
    __syncthreads();
    if (tid == 0) {
        int run = 0;
#pragma unroll
        for (int w = 0; w < 16; w++) { int tmpv = wsum[w]; wsum[w] = run; run += tmpv; }
    }
    __syncthreads();
    if (tid < NBLK) g_bsum[tid] = x - v + wsum[tid >> 5];
}

// Stage 3: add block offsets, set rowptr[NN]
__global__ void scan_add_kernel() {
    int tid = threadIdx.x;
    int i = blockIdx.x * 256 + tid;
    if (i < NN) g_rowptr[i] = g_rowptr[i] + g_bsum[blockIdx.x];
    if (i == 0) g_rowptr[NN] = EE;
}

// scatter with precomputed ranks: NO atomics — pure load/store with deep MLP.
__global__ void scatter_kernel(const int* __restrict__ src, const int* __restrict__ dst) {
    int i = (blockIdx.x * blockDim.x + threadIdx.x) * 8;
    if (i < EE) {
        int4 dva = *(const int4*)&dst[i];
        int4 dvb = *(const int4*)&dst[i + 4];
        int4 sva = *(const int4*)&src[i];
        int4 svb = *(const int4*)&src[i + 4];
        int4 rva = *(const int4*)&g_rank[i];
        int4 rvb = *(const int4*)&g_rank[i + 4];
        g_col[g_rowptr[dva.x] + rva.x] = sva.x;
        g_col[g_rowptr[dva.y] + rva.y] = sva.y;
        g_col[g_rowptr[dva.z] + rva.z] = sva.z;
        g_col[g_rowptr[dva.w] + rva.w] = sva.w;
        g_col[g_rowptr[dvb.x] + rvb.x] = svb.x;
        g_col[g_rowptr[dvb.y] + rvb.y] = svb.y;
        g_col[g_rowptr[dvb.z] + rvb.z] = svb.z;
        g_col[g_rowptr[dvb.w] + rvb.w] = svb.w;
    }
}

// ---------------- layer-1 gather: warp per node, TWO fp32 rows per warp-load ----------------
// Lanes 0..25: sub = lane>=13, f = lane-13*sub. Each 8-load batch covers 16 edges.
// Writes fp32-accumulated sums as fp16 16-half rows (cols 13..15 zero) to g_agg.
__global__ void __launch_bounds__(256)
gather_first_kernel(const float* __restrict__ xin) {
    int warp = (blockIdx.x * 256 + threadIdx.x) >> 5;
    int lane = threadIdx.x & 31;
    int node = warp;
    if (node >= NN) return;
    int sub = (lane >= 13) ? 1 : 0;
    int f = lane - 13 * sub;
    bool active = (lane < 26);
    float acc = 0.f;
    if (active && sub == 0) acc = xin[node * FF + f];   // self term
    int s = g_rowptr[node], e = g_rowptr[node + 1];
    int cidx = (s + lane < e) ? g_col[s + lane] : 0;
#pragma unroll 1
    for (int cb = s; cb < e; cb += 32) {
        int cnt = min(32, e - cb);
        int cidx_next = (cb + 32 + lane < e) ? g_col[cb + 32 + lane] : 0;
        int t = 0;
        for (; t + 16 <= cnt; t += 16) {
            int jj[8];
#pragma unroll
            for (int q = 0; q < 8; q++)
                jj[q] = __shfl_sync(0xffffffffu, cidx, t + 2 * q + sub);
            if (active) {
                float vv[8];
#pragma unroll
                for (int q = 0; q < 8; q++) vv[q] = xin[jj[q] * FF + f];
                acc += ((vv[0] + vv[1]) + (vv[2] + vv[3])) +
                       ((vv[4] + vv[5]) + (vv[6] + vv[7]));
            }
        }
        for (; t + 2 <= cnt; t += 2) {
            int j = __shfl_sync(0xffffffffu, cidx, t + sub);
            if (active) acc += xin[j * FF + f];
        }
        if (t < cnt) {
            int j = __shfl_sync(0xffffffffu, cidx, t);
            if (active && sub == 0) acc += xin[j * FF + f];
        }
        cidx = cidx_next;
    }
    // fold sub1 partial into sub0 lanes
    float other = __shfl_sync(0xffffffffu, acc, (lane + 13) & 31);
    if (lane < 13) acc += other;
    if (lane < 16) g_agg[node * 16 + lane] = __float2half((lane < 13) ? acc : 0.f);
}

// ---------------- hidden-layer gather: warp per node, no smem ----------------
__global__ void __launch_bounds__(256)
gather_hidden_kernel(const __half* __restrict__ xin) {
    int warp = (blockIdx.x * 256 + threadIdx.x) >> 5;
    int lane = threadIdx.x & 31;
    int node = warp;
    if (node >= NN) return;
    const __half2* xin2 = (const __half2*)xin;
    float2 acc = __half22float2(xin2[node * 32 + lane]);
    int s = g_rowptr[node], e = g_rowptr[node + 1];
    int cidx = (s + lane < e) ? g_col[s + lane] : 0;
#pragma unroll 1
    for (int cb = s; cb < e; cb += 32) {
        int cnt = min(32, e - cb);
        int cidx_next = (cb + 32 + lane < e) ? g_col[cb + 32 + lane] : 0;
        int t = 0;
        for (; t + 8 <= cnt; t += 8) {
            int jj[8];
#pragma unroll
            for (int q = 0; q < 8; q++) jj[q] = __shfl_sync(0xffffffffu, cidx, t + q);
            float2 vv[8];
#pragma unroll
            for (int q = 0; q < 8; q++) vv[q] = __half22float2(xin2[jj[q] * 32 + lane]);
            acc.x += ((vv[0].x + vv[1].x) + (vv[2].x + vv[3].x)) +
                     ((vv[4].x + vv[5].x) + (vv[6].x + vv[7].x));
            acc.y += ((vv[0].y + vv[1].y) + (vv[2].y + vv[3].y)) +
                     ((vv[4].y + vv[5].y) + (vv[6].y + vv[7].y));
        }
        for (; t < cnt; t++) {
            int j = __shfl_sync(0xffffffffu, cidx, t);
            float2 vv = __half22float2(xin2[j * 32 + lane]);
            acc.x += vv.x; acc.y += vv.y;
        }
        cidx = cidx_next;
    }
    ((__half2*)g_agg)[node * 32 + lane] = __floats2half2_rn(acc.x, acc.y);
}

// smem layout constants
#define SMEM_ROW_H 72   /* half elements per row (144B): ldmatrix conflict-free */
#define POOL_ROW_F 68   /* float elements per row of pool staging */

// ---------------- layer-1 MLP: reads 16-half g_agg rows (coalesced) ----------------
__global__ void __launch_bounds__(512)
mlp_first_kernel(const float* __restrict__ W1, const float* __restrict__ b1,
                 const float* __restrict__ gam, const float* __restrict__ bet,
                 const float* __restrict__ mu, const float* __restrict__ var,
                 const float* __restrict__ W2, const float* __restrict__ b2,
                 const int* __restrict__ batch,
                 __half* __restrict__ hout, int pool_off) {
    __shared__ __align__(16) __half As[64 * SMEM_ROW_H];
    __shared__ __align__(16) __half W1s[64 * SMEM_ROW_H];
    __shared__ __align__(16) __half W2s[64 * SMEM_ROW_H];
    __shared__ float  Ps[64 * POOL_ROW_F];
    __shared__ float  sc1[64], sh1[64], b2s[64];
    __shared__ int    bgid[64];

    int tid = threadIdx.x;
    int node0 = blockIdx.x * 64;
    int warp = tid >> 5, lane = tid & 31;

    for (int idx = tid; idx < 16 * 64; idx += 512) {
        int krow = idx >> 6, ncol = idx & 63;
        W1s[krow * SMEM_ROW_H + ncol] = __float2half((krow < FF) ? W1[krow * 64 + ncol] : 0.f);
    }
    for (int idx = tid; idx < 64 * 64; idx += 512) {
        int krow = idx >> 6, ncol = idx & 63;
        W2s[krow * SMEM_ROW_H + ncol] = __float2half(W2[krow * 64 + ncol]);
    }
    if (tid < 64) {
        float bn_scale = gam[tid] * rsqrtf(var[tid] + BN_EPS);
        sc1[tid] = bn_scale;
        sh1[tid] = fmaf(b1[tid] - mu[tid], bn_scale, bet[tid]);
        b2s[tid] = b2[tid];
        int node = node0 + tid;
        bgid[tid] = batch[(node < NN) ? node : (NN - 1)];
    }

    // A tile from g_agg (16-half rows): thread t<128 -> row t>>1, 16B chunk t&1
    if (tid < 128) {
        int row = tid >> 1;
        int chk = tid & 1;
        int node = node0 + row;
        uint4 rv = make_uint4(0u, 0u, 0u, 0u);
        if (node < NN) rv = ((const uint4*)g_agg)[(size_t)node * 2 + chk];
        *(uint4*)&As[row * SMEM_ROW_H + chk * 8] = rv;
    }
    __syncthreads();

    int mma_row = warp & 3;
    int mma_col = (warp >> 2) * 16;
    unsigned int base_as = (unsigned int)__cvta_generic_to_shared(As);
    unsigned int base_w1 = (unsigned int)__cvta_generic_to_shared(W1s);
    unsigned int base_w2 = (unsigned int)__cvta_generic_to_shared(W2s);
    int off_a = (mma_row * 16 + (lane & 15)) * SMEM_ROW_H + ((lane >> 4) << 3);
    int off_w = (lane & 15) * SMEM_ROW_H + mma_col + ((lane >> 4) << 3);

    // GEMM1 (KPAD=16 -> single k-chunk)
    float acc1[2][4];
#pragma unroll
    for (int i = 0; i < 2; i++)
#pragma unroll
        for (int j = 0; j < 4; j++) acc1[i][j] = 0.f;
    {
        unsigned int frag_a[4];
        unsigned int frag_b[4];
        gin_ldsm_a(frag_a, base_as + (unsigned int)(off_a * 2));
        gin_ldsm_bt(frag_b, base_w1 + (unsigned int)(off_w * 2));
        gin_mma(acc1[0], frag_a, frag_b[0], frag_b[1]);
        gin_mma(acc1[1], frag_a, frag_b[2], frag_b[3]);
    }
    __syncthreads();

    // epilogue1: BN+ReLU -> As (fp16)
    {
        int row_out = mma_row * 16 + (lane >> 2);
#pragma unroll
        for (int j = 0; j < 2; j++) {
            int c = mma_col + j * 8 + ((lane & 3) << 1);
            float o00 = fmaxf(fmaf(acc1[j][0], sc1[c],     sh1[c]),     0.f);
            float o01 = fmaxf(fmaf(acc1[j][1], sc1[c + 1], sh1[c + 1]), 0.f);
            float o10 = fmaxf(fmaf(acc1[j][2], sc1[c],     sh1[c]),     0.f);
            float o11 = fmaxf(fmaf(acc1[j][3], sc1[c + 1], sh1[c + 1]), 0.f);
            *(__half2*)&As[row_out * SMEM_ROW_H + c]       = __floats2half2_rn(o00, o01);
            *(__half2*)&As[(row_out + 8) * SMEM_ROW_H + c] = __floats2half2_rn(o10, o11);
        }
    }
    __syncthreads();

    // GEMM2 (4 k-chunks)
    float acc2[2][4];
#pragma unroll
    for (int i = 0; i < 2; i++)
#pragma unroll
        for (int j = 0; j < 4; j++) acc2[i][j] = 0.f;
#pragma unroll
    for (int kc = 0; kc < 4; kc++) {
        unsigned int frag_a[4];
        unsigned int frag_b[4];
        gin_ldsm_a(frag_a, base_as + (unsigned int)((off_a + kc * 16) * 2));
        gin_ldsm_bt(frag_b, base_w2 + (unsigned int)((off_w + kc * 16 * SMEM_ROW_H) * 2));
        gin_mma(acc2[0], frag_a, frag_b[0], frag_b[1]);
        gin_mma(acc2[1], frag_a, frag_b[2], frag_b[3]);
    }

    // epilogue2: +b2, ReLU -> hout (fp16) + Ps (f32 staging)
    {
        int row_half = mma_row * 16 + (lane >> 2);
#pragma unroll
        for (int hb = 0; hb < 2; hb++) {
            int r = row_half + hb * 8;
            int node = node0 + r;
            bool valid = (node < NN);
#pragma unroll
            for (int j = 0; j < 2; j++) {
                int c = mma_col + j * 8 + ((lane & 3) << 1);
                float o0 = valid ? fmaxf(acc2[j][hb * 2 + 0] + b2s[c],     0.f) : 0.f;
                float o1 = valid ? fmaxf(acc2[j][hb * 2 + 1] + b2s[c + 1], 0.f) : 0.f;
                if (valid)
                    *(__half2*)&hout[(size_t)node * 64 + c] = __floats2half2_rn(o0, o1);
                *(float2*)&Ps[r * POOL_ROW_F + c] = make_float2(o0, o1);
            }
        }
    }
    __syncthreads();

    // pooled readout: 8 segments of 8 rows
    {
        int col = tid & 63;
        int seg = tid >> 6;
        int rbeg = seg * 8;
        int cur = bgid[rbeg];
        float run = 0.f;
#pragma unroll
        for (int r = rbeg; r < rbeg + 8; r++) {
            int gid = bgid[r];
            if (gid != cur) {
                atomicAdd(&g_pool[cur * POOLW + pool_off + col], run);
                run = 0.f; cur = gid;
            }
            run += Ps[r * POOL_ROW_F + col];
        }
        atomicAdd(&g_pool[cur * POOLW + pool_off + col], run);
    }
}

// ---------------- hidden-layer MLP: reads pre-gathered g_agg (64-half rows) ----------------
__global__ void __launch_bounds__(512)
mlp_hidden_kernel(const float* __restrict__ W1, const float* __restrict__ b1,
                  const float* __restrict__ gam, const float* __restrict__ bet,
                  const float* __restrict__ mu, const float* __restrict__ var,
                  const float* __restrict__ W2, const float* __restrict__ b2,
                  const int* __restrict__ batch,
                  __half* __restrict__ hout, int pool_off) {
    __shared__ __align__(16) __half As[64 * SMEM_ROW_H];
    __shared__ __align__(16) __half W1s[64 * SMEM_ROW_H];
    __shared__ __align__(16) __half W2s[64 * SMEM_ROW_H];
    __shared__ float  Ps[64 * POOL_ROW_F];
    __shared__ float  sc1[64], sh1[64], b2s[64];
    __shared__ int    bgid[64];

    int tid = threadIdx.x;
    int node0 = blockIdx.x * 64;
    int warp = tid >> 5, lane = tid & 31;

    for (int idx = tid; idx < 64 * 64; idx += 512) {
        int krow = idx >> 6, ncol = idx & 63;
        W1s[krow * SMEM_ROW_H + ncol] = __float2half(W1[krow * 64 + ncol]);
        W2s[krow * SMEM_ROW_H + ncol] = __float2half(W2[krow * 64 + ncol]);
    }
    if (tid < 64) {
        float bn_scale = gam[tid] * rsqrtf(var[tid] + BN_EPS);
        sc1[tid] = bn_scale;
        sh1[tid] = fmaf(b1[tid] - mu[tid], bn_scale, bet[tid]);
        b2s[tid] = b2[tid];
        int node = node0 + tid;
        bgid[tid] = batch[(node < NN) ? node : (NN - 1)];
    }

    // Load A tile from g_agg: thread t -> row t>>3, 16B chunk t&7 (one pass, coalesced)
    {
        int row = tid >> 3;
        int chk = tid & 7;
        int node = node0 + row;
        uint4 rv = make_uint4(0u, 0u, 0u, 0u);
        if (node < NN) rv = ((const uint4*)g_agg)[(size_t)node * 8 + chk];
        *(uint4*)&As[row * SMEM_ROW_H + chk * 8] = rv;
    }
    __syncthreads();

    int mma_row = warp & 3;
    int mma_col = (warp >> 2) * 16;
    unsigned int base_as = (unsigned int)__cvta_generic_to_shared(As);
    unsigned int base_w1 = (unsigned int)__cvta_generic_to_shared(W1s);
    unsigned int base_w2 = (unsigned int)__cvta_generic_to_shared(W2s);
    int off_a = (mma_row * 16 + (lane & 15)) * SMEM_ROW_H + ((lane >> 4) << 3);
    int off_w = (lane & 15) * SMEM_ROW_H + mma_col + ((lane >> 4) << 3);

    // GEMM1 (4 k-chunks)
    float acc1[2][4];
#pragma unroll
    for (int i = 0; i < 2; i++)
#pragma unroll
        for (int j = 0; j < 4; j++) acc1[i][j] = 0.f;
#pragma unroll
    for (int kc = 0; kc < 4; kc++) {
        unsigned int frag_a[4];
        unsigned int frag_b[4];
        gin_ldsm_a(frag_a, base_as + (unsigned int)((off_a + kc * 16) * 2));
        gin_ldsm_bt(frag_b, base_w1 + (unsigned int)((off_w + kc * 16 * SMEM_ROW_H) * 2));
        gin_mma(acc1[0], frag_a, frag_b[0], frag_b[1]);
        gin_mma(acc1[1], frag_a, frag_b[2], frag_b[3]);
    }
    __syncthreads();

    // epilogue1: BN+ReLU -> As (fp16)
    {
        int row_out = mma_row * 16 + (lane >> 2);
#pragma unroll
        for (int j = 0; j < 2; j++) {
            int c = mma_col + j * 8 + ((lane & 3) << 1);
            float o00 = fmaxf(fmaf(acc1[j][0], sc1[c],     sh1[c]),     0.f);
            float o01 = fmaxf(fmaf(acc1[j][1], sc1[c + 1], sh1[c + 1]), 0.f);
            float o10 = fmaxf(fmaf(acc1[j][2], sc1[c],     sh1[c]),     0.f);
            float o11 = fmaxf(fmaf(acc1[j][3], sc1[c + 1], sh1[c + 1]), 0.f);
            *(__half2*)&As[row_out * SMEM_ROW_H + c]       = __floats2half2_rn(o00, o01);
            *(__half2*)&As[(row_out + 8) * SMEM_ROW_H + c] = __floats2half2_rn(o10, o11);
        }
    }
    __syncthreads();

    // GEMM2
    float acc2[2][4];
#pragma unroll
    for (int i = 0; i < 2; i++)
#pragma unroll
        for (int j = 0; j < 4; j++) acc2[i][j] = 0.f;
#pragma unroll
    for (int kc = 0; kc < 4; kc++) {
        unsigned int frag_a[4];
        unsigned int frag_b[4];
        gin_ldsm_a(frag_a, base_as + (unsigned int)((off_a + kc * 16) * 2));
        gin_ldsm_bt(frag_b, base_w2 + (unsigned int)((off_w + kc * 16 * SMEM_ROW_H) * 2));
        gin_mma(acc2[0], frag_a, frag_b[0], frag_b[1]);
        gin_mma(acc2[1], frag_a, frag_b[2], frag_b[3]);
    }

    // epilogue2: +b2, ReLU -> hout (fp16) + Ps (f32 staging)
    {
        int row_half = mma_row * 16 + (lane >> 2);
#pragma unroll
        for (int hb = 0; hb < 2; hb++) {
            int r = row_half + hb * 8;
            int node = node0 + r;
            bool valid = (node < NN);
#pragma unroll
            for (int j = 0; j < 2; j++) {
                int c = mma_col + j * 8 + ((lane & 3) << 1);
                float o0 = valid ? fmaxf(acc2[j][hb * 2 + 0] + b2s[c],     0.f) : 0.f;
                float o1 = valid ? fmaxf(acc2[j][hb * 2 + 1] + b2s[c + 1], 0.f) : 0.f;
                if (valid)
                    *(__half2*)&hout[(size_t)node * 64 + c] = __floats2half2_rn(o0, o1);
                *(float2*)&Ps[r * POOL_ROW_F + c] = make_float2(o0, o1);
            }
        }
    }
    __syncthreads();

    // pooled readout: 8 segments of 8 rows
    {
        int col = tid & 63;
        int seg = tid >> 6;
        int rbeg = seg * 8;
        int cur = bgid[rbeg];
        float run = 0.f;
#pragma unroll
        for (int r = rbeg; r < rbeg + 8; r++) {
            int gid = bgid[r];
            if (gid != cur) {
                atomicAdd(&g_pool[cur * POOLW + pool_off + col], run);
                run = 0.f; cur = gid;
            }
            run += Ps[r * POOL_ROW_F + col];
        }
        atomicAdd(&g_pool[cur * POOLW + pool_off + col], run);
    }
}

// ---------------- head: fc1(192->192)+ReLU, fc2(192->2), log_softmax ----------------
__global__ void head_kernel(const float* __restrict__ fc1W, const float* __restrict__ fc1b,
                            const float* __restrict__ fc2W, const float* __restrict__ fc2b,
                            float* __restrict__ out) {
    __shared__ float h[POOLW];
    __shared__ float h2[POOLW];
    __shared__ float r0s[6], r1s[6];
    int g = blockIdx.x, t = threadIdx.x;
    h[t] = g_pool[g * POOLW + t];
    __syncthreads();
    float acc = fc1b[t];
#pragma unroll 8
    for (int k = 0; k < POOLW; k++) acc = fmaf(h[k], fc1W[k * POOLW + t], acc);
    h2[t] = fmaxf(acc, 0.f);
    __syncthreads();
    float p0 = h2[t] * fc2W[t * 2 + 0];
    float p1 = h2[t] * fc2W[t * 2 + 1];
#pragma unroll
    for (int o = 16; o > 0; o >>= 1) {
        p0 += __shfl_down_sync(0xffffffffu, p0, o);
        p1 += __shfl_down_sync(0xffffffffu, p1, o);
    }
    if ((t & 31) == 0) { r0s[t >> 5] = p0; r1s[t >> 5] = p1; }
    __syncthreads();
    if (t == 0) {
        float z0 = fc2b[0], z1 = fc2b[1];
#pragma unroll
        for (int w = 0; w < 6; w++) { z0 += r0s[w]; z1 += r1s[w]; }
        float mx = fmaxf(z0, z1);
        float lse = mx + logf(expf(z0 - mx) + expf(z1 - mx));
        out[g * 2 + 0] = z0 - lse;
        out[g * 2 + 1] = z1 - lse;
    }
}

// ---------------- launch ----------------
extern "C" void kernel_launch(void* const* d_in, const int* in_sizes, int n_in,
                              void* d_out, int out_size) {
    const float* x     = (const float*)d_in[0];
    const int*   src   = (const int*)d_in[1];
    const int*   dst   = (const int*)d_in[2];
    const int*   batch = (const int*)d_in[3];

    const float* c1p[8]; for (int i = 0; i < 8; i++) c1p[i] = (const float*)d_in[4 + i];
    const float* c2p[8]; for (int i = 0; i < 8; i++) c2p[i] = (const float*)d_in[12 + i];
    const float* c3p[8]; for (int i = 0; i < 8; i++) c3p[i] = (const float*)d_in[20 + i];
    const float* fc1W = (const float*)d_in[28];
    const float* fc1b = (const float*)d_in[29];
    const float* fc2W = (const float*)d_in[30];
    const float* fc2b = (const float*)d_in[31];
    float* out = (float*)d_out;

    __half *hA_p, *hB_p;
    cudaGetSymbolAddress((void**)&hA_p, g_hA);
    cudaGetSymbolAddress((void**)&hB_p, g_hB);

    const int TPB = 256;
    int blkN = (NN + TPB - 1) / TPB;                 // 391
    int blkE8 = (EE / 8 + TPB - 1) / TPB;            // 1563 (8 edges/thread)
    int blkM = (NN + 63) / 64;                       // 1563
    int blkG = (NN * 32 + TPB - 1) / TPB;            // 12500 (warp per node)

    // CSR build (hist computes per-edge rank; scatter is atomic-free)
    init_zero_kernel<<<blkN, TPB>>>();
    hist_kernel<<<blkE8, TPB>>>(dst);
    scan_block_kernel<<<NBLK, 256>>>();
    scan_bsum_kernel<<<1, 512>>>();
    scan_add_kernel<<<NBLK, 256>>>();
    scatter_kernel<<<blkE8, TPB>>>(src, dst);

    // layer 1: high-occupancy 2-row gather, then coalesced MLP
    gather_first_kernel<<<blkG, TPB>>>(x);
    mlp_first_kernel<<<blkM, 512>>>(c1p[0], c1p[1], c1p[2], c1p[3], c1p[4],
                                    c1p[5], c1p[6], c1p[7], batch, hA_p, 0);
    // layer 2
    gather_hidden_kernel<<<blkG, TPB>>>(hA_p);
    mlp_hidden_kernel<<<blkM, 512>>>(c2p[0], c2p[1], c2p[2], c2p[3], c2p[4],
                                     c2p[5], c2p[6], c2p[7], batch, hB_p, 64);
    // layer 3
    gather_hidden_kernel<<<blkG, TPB>>>(hB_p);
    mlp_hidden_kernel<<<blkM, 512>>>(c3p[0], c3p[1], c3p[2], c3p[3], c3p[4],
                                     c3p[5], c3p[6], c3p[7], batch, hA_p, 128);

    // readout head
    head_kernel<<<GG, POOLW>>>(fc1W, fc1b, fc2W, fc2b, out);
}